// round 8
// baseline (speedup 1.0000x reference)
#include <cuda_runtime.h>
#include <cuda_fp16.h>
#include <math.h>
#include <float.h>
#include <stdint.h>

#define BB 32768
#define DD 256
#define KK 4096
#define NPOOL 30   // 24 tensor (8 thr x top-3) + 6 ffma (2 warps x top-3)

// ---- scratch (static device globals: allocation-free) ----
__device__ float          g_wsq[KK];
__device__ unsigned int   g_counts[KK];
__device__ double         g_loss;
__device__ unsigned int   g_done;
__device__ __half         g_w16[KK * DD];    // f16(w * 4096)
__device__ float          g_cval[BB * NPOOL];
__device__ int            g_cidx[BB * NPOOL];

// ---------------- helpers ----------------
__device__ __forceinline__ uint32_t smem_u32(const void* p) {
    return (uint32_t)__cvta_generic_to_shared(p);
}
__device__ __forceinline__ void cp16(uint32_t dst, const void* src) {
    asm volatile("cp.async.cg.shared.global [%0], [%1], 16;" :: "r"(dst), "l"(src));
}
__device__ __forceinline__ void cp_commit() {
    asm volatile("cp.async.commit_group;" ::: "memory");
}
template <int N> __device__ __forceinline__ void cp_wait() {
    asm volatile("cp.async.wait_group %0;" :: "n"(N) : "memory");
}
__device__ __forceinline__ uint32_t swz(uint32_t off) {
    return off ^ ((off >> 3) & 0x70);
}
__device__ __forceinline__ void ldsm4(uint32_t* r, uint32_t addr) {
    asm volatile("ldmatrix.sync.aligned.m8n8.x4.shared.b16 {%0,%1,%2,%3}, [%4];"
                 : "=r"(r[0]), "=r"(r[1]), "=r"(r[2]), "=r"(r[3]) : "r"(addr));
}
__device__ __forceinline__ void ldsm2(uint32_t* r, uint32_t addr) {
    asm volatile("ldmatrix.sync.aligned.m8n8.x2.shared.b16 {%0,%1}, [%2];"
                 : "=r"(r[0]), "=r"(r[1]) : "r"(addr));
}
// f16 inputs, f16 accumulators (2 regs)
__device__ __forceinline__ void mma16816h(uint32_t* c, const uint32_t* a,
                                          const uint32_t* b) {
    asm volatile(
        "mma.sync.aligned.m16n8k16.row.col.f16.f16.f16.f16 "
        "{%0,%1}, {%2,%3,%4,%5}, {%6,%7}, {%0,%1};"
        : "+r"(c[0]), "+r"(c[1])
        : "r"(a[0]), "r"(a[1]), "r"(a[2]), "r"(a[3]), "r"(b[0]), "r"(b[1]));
}
__device__ __forceinline__ uint32_t lds32(uint32_t a) {
    uint32_t v;
    asm volatile("ld.shared.b32 %0, [%1];" : "=r"(v) : "r"(a));
    return v;
}

// ---------------- pass-1 smem layout (bytes) ----------------
// z f16: 4 slices x [128 rows x 64 f16] = 65536
// w ring: 2 x (swizzled 16384 + unswizzled 2048) = 36864
#define ZH_OFF    0u
#define W_OFF     65536u
#define RSZ       18432u
#define SMEM_BYTES 102400u

// ---------------------------------------------------------------------------
// Kernel A: codebook -> f16 (scaled by 4096), fp32 norms, zero accumulators.
// ---------------------------------------------------------------------------
__global__ void conv_w(const float* __restrict__ cb) {
    int r = blockIdx.x * 8 + (threadIdx.x >> 5);
    int lane = threadIdx.x & 31;
    const float* wr = cb + (size_t)r * DD + lane * 8;
    float4 a = *(const float4*)wr;
    float4 b = *(const float4*)(wr + 4);
    float s = a.x * a.x + a.y * a.y + a.z * a.z + a.w * a.w +
              b.x * b.x + b.y * b.y + b.z * b.z + b.w * b.w;
    const float sc = 4096.f;
    __half2 h0 = __float22half2_rn(make_float2(a.x * sc, a.y * sc));
    __half2 h1 = __float22half2_rn(make_float2(a.z * sc, a.w * sc));
    __half2 h2 = __float22half2_rn(make_float2(b.x * sc, b.y * sc));
    __half2 h3 = __float22half2_rn(make_float2(b.z * sc, b.w * sc));
    uint4 pk;
    pk.x = *(uint32_t*)&h0; pk.y = *(uint32_t*)&h1;
    pk.z = *(uint32_t*)&h2; pk.w = *(uint32_t*)&h3;
    *(uint4*)(g_w16 + (size_t)r * DD + lane * 8) = pk;
    #pragma unroll
    for (int o = 16; o > 0; o >>= 1) s += __shfl_xor_sync(0xffffffffu, s, o);
    if (lane == 0) { g_wsq[r] = s; g_counts[r] = 0u; }
    if (r == 0 && lane == 0) { g_loss = 0.0; g_done = 0u; }
}

// ---------------------------------------------------------------------------
// w-slice loader: slice j = (chunk j>>2, dslice j&3).
// tid<256: 128 codes x 64 dims f16, swizzled.
// tid>=256: codes 112..127 unswizzled copy (for FFMA warps).
// ---------------------------------------------------------------------------
__device__ __forceinline__ void load_wslice(int j, int bufj, uint32_t sb, int tid) {
    const int ch = j >> 2, s = j & 3;
    const uint32_t base = sb + W_OFF + (uint32_t)bufj * RSZ;
    if (tid < 256) {
        #pragma unroll
        for (int i = 0; i < 4; ++i) {
            int flat = i * 256 + tid;        // 1024 16B-chunks
            int n = flat >> 3, c = flat & 7;
            uint32_t off = swz((uint32_t)(n * 128 + c * 16));
            cp16(base + off, g_w16 + (size_t)(ch * 128 + n) * DD + s * 64 + c * 8);
        }
    } else {
        int t = tid - 256;                   // 0..63, 128 chunks total
        #pragma unroll
        for (int i = 0; i < 2; ++i) {
            int flat = t * 2 + i;
            int n = flat >> 3, c = flat & 7;
            cp16(base + 16384u + (uint32_t)(n * 128 + c * 16),
                 g_w16 + (size_t)(ch * 128 + 112 + n) * DD + s * 64 + c * 8);
        }
    }
}

// ---------------------------------------------------------------------------
// Pass 1 (hybrid): 8 tensor warps (codes 0..111 per chunk, warp tile 32x56)
// + 2 HFMA2 warps (codes 112..127 per chunk) sharing the cp.async ring.
// Per-thread top-3 candidate pools merged in pass 2.
// ---------------------------------------------------------------------------
__global__ void __launch_bounds__(320, 2)
vq_pass1(const float* __restrict__ z) {
    extern __shared__ __align__(1024) char smem[];
    const uint32_t sb = smem_u32(smem);
    const int tid = threadIdx.x;
    const int lane = tid & 31;
    const int warp = tid >> 5;
    const int row0 = blockIdx.x * 128;

    // prefetch w slices 0,1
    load_wslice(0, 0, sb, tid); cp_commit();
    load_wslice(1, 1, sb, tid); cp_commit();

    // ---- stage z fp32 -> f16 into smem (tid<256) ----
    if (tid < 256) {
        #pragma unroll
        for (int i = 0; i < 32; ++i) {
            int flat = i * 256 + tid;            // 8192 float4
            int r = flat >> 6, d4 = flat & 63;
            float4 v = *(const float4*)(z + (size_t)(row0 + r) * DD + d4 * 4);
            __half2 p0 = __float22half2_rn(make_float2(v.x, v.y));
            __half2 p1 = __float22half2_rn(make_float2(v.z, v.w));
            uint2 pk;
            pk.x = *(uint32_t*)&p0; pk.y = *(uint32_t*)&p1;
            uint32_t off = swz((uint32_t)((d4 >> 4) * 16384 + r * 128 + (d4 & 15) * 8));
            *(uint2*)(smem + ZH_OFF + off) = pk;
        }
    }

    if (warp < 8) {
        // ================= tensor warps =================
        const int wm = warp >> 1;        // 0..3 (M)
        const int wn = warp & 1;         // 0..1 (N)
        const int g = lane >> 3;
        const int l7 = lane & 7;

        float b0v[4], b1v[4], b2v[4];
        int   b0i[4], b1i[4], b2i[4];
        #pragma unroll
        for (int i = 0; i < 4; ++i) {
            b0v[i] = -FLT_MAX; b1v[i] = -FLT_MAX; b2v[i] = -FLT_MAX;
            b0i[i] = 0; b1i[i] = 0; b2i[i] = 0;
        }

        uint32_t acc[2][7][2];   // f16x2 accumulators, 7 n-frags

        for (int idx = 0; idx < 128; ++idx) {
            const int ch = idx >> 2, s = idx & 3, buf = idx & 1;

            cp_wait<1>();
            __syncthreads();

            if (s == 0) {
                #pragma unroll
                for (int mf = 0; mf < 2; ++mf)
                    #pragma unroll
                    for (int nf = 0; nf < 7; ++nf) {
                        acc[mf][nf][0] = 0u; acc[mf][nf][1] = 0u;
                    }
            }

            const uint32_t wbase = sb + W_OFF + (uint32_t)buf * RSZ;
            #pragma unroll
            for (int ks = 0; ks < 4; ++ks) {
                uint32_t ah[2][4];
                #pragma unroll
                for (int mf = 0; mf < 2; ++mf) {
                    uint32_t off = (uint32_t)((wm * 32 + mf * 16 + (g & 1) * 8 + l7) * 128
                                              + ks * 32 + ((g >> 1) << 4));
                    ldsm4(ah[mf], sb + ZH_OFF + swz(off) + (uint32_t)(s * 16384));
                }
                uint32_t bh[3][4];
                uint32_t bx[2];
                #pragma unroll
                for (int p = 0; p < 3; ++p) {
                    uint32_t off = (uint32_t)((wn * 56 + p * 16 + ((g >> 1) << 3) + l7) * 128
                                              + ks * 32 + ((g & 1) << 4));
                    ldsm4(bh[p], wbase + swz(off));
                }
                {   // last 8 codes (nf=6): x2, lanes 0-15 provide addresses
                    uint32_t off = (uint32_t)((wn * 56 + 48 + l7) * 128
                                              + ks * 32 + ((g & 1) << 4));
                    ldsm2(bx, wbase + swz(off));
                }
                #pragma unroll
                for (int mf = 0; mf < 2; ++mf) {
                    #pragma unroll
                    for (int p = 0; p < 3; ++p) {
                        mma16816h(acc[mf][2 * p],     ah[mf], &bh[p][0]);
                        mma16816h(acc[mf][2 * p + 1], ah[mf], &bh[p][2]);
                    }
                    mma16816h(acc[mf][6], ah[mf], bx);
                }
            }

            __syncthreads();
            if (idx + 2 < 128) load_wslice(idx + 2, buf, sb, tid);
            cp_commit();

            if (s == 3) {
                #pragma unroll
                for (int nf = 0; nf < 7; ++nf) {
                    int col0 = ch * 128 + wn * 56 + nf * 8 + (lane & 3) * 2;
                    #pragma unroll
                    for (int mf = 0; mf < 2; ++mf) {
                        float2 p01 = __half22float2(*(__half2*)&acc[mf][nf][0]);
                        float2 p23 = __half22float2(*(__half2*)&acc[mf][nf][1]);
                        float vq[4] = {p01.x, p01.y, p23.x, p23.y};
                        #pragma unroll
                        for (int q = 0; q < 4; ++q) {
                            int sl = mf * 2 + (q >> 1);
                            float v = vq[q];
                            int c = col0 + (q & 1);
                            if (v > b2v[sl]) {
                                if (v > b1v[sl]) {
                                    b2v[sl] = b1v[sl]; b2i[sl] = b1i[sl];
                                    if (v > b0v[sl]) {
                                        b1v[sl] = b0v[sl]; b1i[sl] = b0i[sl];
                                        b0v[sl] = v;       b0i[sl] = c;
                                    } else { b1v[sl] = v; b1i[sl] = c; }
                                } else { b2v[sl] = v; b2i[sl] = c; }
                            }
                        }
                    }
                }
            }
        }

        #pragma unroll
        for (int sl = 0; sl < 4; ++sl) {
            int r = row0 + wm * 32 + (sl >> 1) * 16 + (sl & 1) * 8 + (lane >> 2);
            int base = r * NPOOL + (wn * 4 + (lane & 3)) * 3;
            g_cval[base]     = b0v[sl]; g_cidx[base]     = b0i[sl];
            g_cval[base + 1] = b1v[sl]; g_cidx[base + 1] = b1i[sl];
            g_cval[base + 2] = b2v[sl]; g_cidx[base + 2] = b2i[sl];
        }
    } else {
        // ================= HFMA2 warps (codes 112..127) =================
        const int ffa = warp - 8;              // 0/1: codes 112+8*ffa..+8
        const uint32_t mr = (uint32_t)((lane & 7) << 4);   // z swizzle const

        float t0v[4], t1v[4], t2v[4];
        int   t0i[4], t1i[4], t2i[4];
        #pragma unroll
        for (int i = 0; i < 4; ++i) {
            t0v[i] = -FLT_MAX; t1v[i] = -FLT_MAX; t2v[i] = -FLT_MAX;
            t0i[i] = 0; t1i[i] = 0; t2i[i] = 0;
        }

        __half2 acc[4][8];

        for (int idx = 0; idx < 128; ++idx) {
            const int ch = idx >> 2, s = idx & 3, buf = idx & 1;

            cp_wait<1>();
            __syncthreads();

            if (s == 0) {
                #pragma unroll
                for (int rj = 0; rj < 4; ++rj)
                    #pragma unroll
                    for (int j = 0; j < 8; ++j)
                        acc[rj][j] = __half2half2(__ushort_as_half(0));
            }

            const uint32_t wu = sb + W_OFF + (uint32_t)buf * RSZ + 16384u
                                + (uint32_t)(ffa * 1024);
            const uint32_t zb = sb + ZH_OFF + (uint32_t)(s * 16384);
            #pragma unroll 8
            for (int c = 0; c < 32; ++c) {
                uint32_t x = (uint32_t)(c * 4);
                __half2 wz[8];
                #pragma unroll
                for (int j = 0; j < 8; ++j) {
                    uint32_t u = lds32(wu + (uint32_t)(j * 128) + x);
                    wz[j] = *(__half2*)&u;
                }
                #pragma unroll
                for (int rj = 0; rj < 4; ++rj) {
                    uint32_t u = lds32(zb + (uint32_t)((lane + 32 * rj) * 128)
                                       + (x ^ mr));
                    __half2 zz = *(__half2*)&u;
                    #pragma unroll
                    for (int j = 0; j < 8; ++j)
                        acc[rj][j] = __hfma2(zz, wz[j], acc[rj][j]);
                }
            }

            __syncthreads();
            if (idx + 2 < 128) load_wslice(idx + 2, buf, sb, tid);
            cp_commit();

            if (s == 3) {
                #pragma unroll
                for (int rj = 0; rj < 4; ++rj) {
                    #pragma unroll
                    for (int j = 0; j < 8; ++j) {
                        float v = __low2float(acc[rj][j]) + __high2float(acc[rj][j]);
                        int c = ch * 128 + 112 + ffa * 8 + j;
                        if (v > t2v[rj]) {
                            if (v > t1v[rj]) {
                                t2v[rj] = t1v[rj]; t2i[rj] = t1i[rj];
                                if (v > t0v[rj]) {
                                    t1v[rj] = t0v[rj]; t1i[rj] = t0i[rj];
                                    t0v[rj] = v;       t0i[rj] = c;
                                } else { t1v[rj] = v; t1i[rj] = c; }
                            } else { t2v[rj] = v; t2i[rj] = c; }
                        }
                    }
                }
            }
        }

        #pragma unroll
        for (int rj = 0; rj < 4; ++rj) {
            int r = row0 + lane + 32 * rj;
            int base = r * NPOOL + 24 + ffa * 3;
            g_cval[base]     = t0v[rj]; g_cidx[base]     = t0i[rj];
            g_cval[base + 1] = t1v[rj]; g_cidx[base + 1] = t1i[rj];
            g_cval[base + 2] = t2v[rj]; g_cidx[base + 2] = t2i[rj];
        }
    }
}

// ---------------------------------------------------------------------------
// Pass 2 (fused output + final): per row, exact fp32 rescore of the top-8
// pool candidates with reference rounding fl(fl(zsq+wsq) - 2*dot) and
// first-index tie-break; write z_q, index, histogram, loss. Last block
// computes the loss/perplexity scalars.
// NOTE: dot/zsq summation orders identical to rounds 3-7 (proven vs reference).
// ---------------------------------------------------------------------------
__global__ void __launch_bounds__(256)
vq_rescore(const float* __restrict__ z, const float* __restrict__ cb,
           float* __restrict__ out, int out_size) {
    const int lane = threadIdx.x & 31;
    const int row = blockIdx.x * 8 + (threadIdx.x >> 5);

    // z row: 8 dims per lane
    float zr[8];
    {
        float4 a = *(const float4*)(z + (size_t)row * DD + lane * 8);
        float4 b = *(const float4*)(z + (size_t)row * DD + lane * 8 + 4);
        zr[0] = a.x; zr[1] = a.y; zr[2] = a.z; zr[3] = a.w;
        zr[4] = b.x; zr[5] = b.y; zr[6] = b.z; zr[7] = b.w;
    }
    float zsq = 0.f;
    #pragma unroll
    for (int k = 0; k < 8; ++k) zsq += zr[k] * zr[k];
    #pragma unroll
    for (int o = 16; o > 0; o >>= 1) zsq += __shfl_xor_sync(0xffffffffu, zsq, o);

    // candidate pool
    float cv = -FLT_MAX; int ci = 0x7fffffff;
    if (lane < NPOOL) { cv = g_cval[row * NPOOL + lane]; ci = g_cidx[row * NPOOL + lane]; }

    // select top-8 candidates by approx dot (shfl only)
    int cand[8];
    #pragma unroll
    for (int t = 0; t < 8; ++t) {
        float m = cv; int mi = ci;
        #pragma unroll
        for (int o = 16; o > 0; o >>= 1) {
            float mv = __shfl_xor_sync(0xffffffffu, m, o);
            int   mj = __shfl_xor_sync(0xffffffffu, mi, o);
            if (mv > m || (mv == m && mj < mi)) { m = mv; mi = mj; }
        }
        cand[t] = mi;
        if (ci == mi) cv = -FLT_MAX;
    }

    // prefetch all 8 candidate rows (MLP=16)
    float4 wa[8], wb[8];
    #pragma unroll
    for (int t = 0; t < 8; ++t) {
        const float* wp = cb + (size_t)cand[t] * DD + lane * 8;
        wa[t] = *(const float4*)wp;
        wb[t] = *(const float4*)(wp + 4);
    }

    // exact fp32 partial dots (same fma order as prior rounds)
    float dp[8];
    #pragma unroll
    for (int t = 0; t < 8; ++t) {
        float d = 0.f;
        d = fmaf(zr[0], wa[t].x, d); d = fmaf(zr[1], wa[t].y, d);
        d = fmaf(zr[2], wa[t].z, d); d = fmaf(zr[3], wa[t].w, d);
        d = fmaf(zr[4], wb[t].x, d); d = fmaf(zr[5], wb[t].y, d);
        d = fmaf(zr[6], wb[t].z, d); d = fmaf(zr[7], wb[t].w, d);
        dp[t] = d;
    }
    #pragma unroll
    for (int o = 16; o > 0; o >>= 1) {
        #pragma unroll
        for (int t = 0; t < 8; ++t)
            dp[t] += __shfl_xor_sync(0xffffffffu, dp[t], o);
    }

    float bdist = FLT_MAX;
    int   widx = 0x7fffffff;
    #pragma unroll
    for (int t = 0; t < 8; ++t) {
        float dist = (zsq + __ldg(&g_wsq[cand[t]])) - 2.f * dp[t];
        if (dist < bdist || (dist == bdist && cand[t] < widx)) {
            bdist = dist; widx = cand[t];
        }
    }

    // outputs: gather winner row (L2 hit)
    const float* wp = cb + (size_t)widx * DD + lane * 8;
    float4 a = *(const float4*)wp;
    float4 b = *(const float4*)(wp + 4);
    float lsum = 0.f;
    {
        float* op = out + (size_t)row * DD + lane * 8;
        if ((row + 1) * DD <= out_size) {
            *(float4*)op = a;
            *(float4*)(op + 4) = b;
        }
        float w8[8] = {a.x, a.y, a.z, a.w, b.x, b.y, b.z, b.w};
        #pragma unroll
        for (int k = 0; k < 8; ++k) {
            float dd = w8[k] - zr[k];
            lsum += dd * dd;
        }
    }
    #pragma unroll
    for (int o = 16; o > 0; o >>= 1) lsum += __shfl_xor_sync(0xffffffffu, lsum, o);

    if (lane == 0) {
        atomicAdd(&g_counts[widx], 1u);
        atomicAdd(&g_loss, (double)lsum);
        int pos = BB * DD + row;
        if (pos < out_size) out[pos] = (float)widx;
        __threadfence();
    }

    // ---- fused finalization: last block computes scalars ----
    __shared__ int slast;
    __shared__ double red[8];
    __syncthreads();
    if (threadIdx.x == 0)
        slast = (atomicAdd(&g_done, 1u) == (unsigned)(gridDim.x - 1)) ? 1 : 0;
    __syncthreads();
    if (slast) {
        int t = threadIdx.x;
        double s = 0.0;
        for (int k = t; k < KK; k += 256) {
            unsigned c = atomicAdd(&g_counts[k], 0u);   // coherent read
            float p = (float)c / (float)BB;
            s += (double)(p * logf(p + 1e-10f));
        }
        #pragma unroll
        for (int o = 16; o > 0; o >>= 1) s += __shfl_xor_sync(0xffffffffu, s, o);
        if ((t & 31) == 0) red[t >> 5] = s;
        __syncthreads();
        if (t < 32) {
            double v = (t < 8) ? red[t] : 0.0;
            #pragma unroll
            for (int o = 4; o > 0; o >>= 1) v += __shfl_xor_sync(0xffffffffu, v, o);
            if (t == 0) {
                double loss = atomicAdd(&g_loss, 0.0);  // coherent read
                int p0 = BB * DD + BB;
                if (p0 < out_size)
                    out[p0] = (float)(loss / ((double)BB * (double)DD) * 1.25);
                if (p0 + 1 < out_size)
                    out[p0 + 1] = expf((float)(-v));
            }
        }
    }
}

// ---------------------------------------------------------------------------
extern "C" void kernel_launch(void* const* d_in, const int* in_sizes, int n_in,
                              void* d_out, int out_size) {
    const float* z  = (const float*)d_in[0];   // z_e [32768, 256] f32
    const float* cb = (const float*)d_in[1];   // codebook [4096, 256] f32
    float* out = (float*)d_out;

    cudaFuncSetAttribute(vq_pass1,
                         cudaFuncAttributeMaxDynamicSharedMemorySize, SMEM_BYTES);

    conv_w<<<KK / 8, 256>>>(cb);
    vq_pass1<<<BB / 128, 320, SMEM_BYTES>>>(z);
    vq_rescore<<<BB / 8, 256>>>(z, cb, out, out_size);
}

// round 9
// speedup vs baseline: 1.7871x; 1.7871x over previous
#include <cuda_runtime.h>
#include <cuda_fp16.h>
#include <math.h>
#include <float.h>
#include <stdint.h>

#define BB 32768
#define DD 256
#define KK 4096
#define NPOOL 24   // 8 threads/row x top-3

// ---- scratch (static device globals: allocation-free) ----
__device__ float          g_wsq[KK];
__device__ unsigned int   g_counts[KK];
__device__ double         g_loss;
__device__ unsigned int   g_done;
__device__ __half         g_w16[KK * DD];    // f16(w * 4096)
__device__ float          g_cval[BB * NPOOL];
__device__ int            g_cidx[BB * NPOOL];

// ---------------- helpers ----------------
__device__ __forceinline__ uint32_t smem_u32(const void* p) {
    return (uint32_t)__cvta_generic_to_shared(p);
}
__device__ __forceinline__ void cp16(uint32_t dst, const void* src) {
    asm volatile("cp.async.cg.shared.global [%0], [%1], 16;" :: "r"(dst), "l"(src));
}
__device__ __forceinline__ void cp_commit() {
    asm volatile("cp.async.commit_group;" ::: "memory");
}
template <int N> __device__ __forceinline__ void cp_wait() {
    asm volatile("cp.async.wait_group %0;" :: "n"(N) : "memory");
}
__device__ __forceinline__ uint32_t swz(uint32_t off) {
    return off ^ ((off >> 3) & 0x70);
}
__device__ __forceinline__ void ldsm4(uint32_t* r, uint32_t addr) {
    asm volatile("ldmatrix.sync.aligned.m8n8.x4.shared.b16 {%0,%1,%2,%3}, [%4];"
                 : "=r"(r[0]), "=r"(r[1]), "=r"(r[2]), "=r"(r[3]) : "r"(addr));
}
// f16 inputs, f16 accumulators (2 regs)
__device__ __forceinline__ void mma16816h(uint32_t* c, const uint32_t* a,
                                          const uint32_t* b) {
    asm volatile(
        "mma.sync.aligned.m16n8k16.row.col.f16.f16.f16.f16 "
        "{%0,%1}, {%2,%3,%4,%5}, {%6,%7}, {%0,%1};"
        : "+r"(c[0]), "+r"(c[1])
        : "r"(a[0]), "r"(a[1]), "r"(a[2]), "r"(a[3]), "r"(b[0]), "r"(b[1]));
}

// ---------------- pass-1 smem layout (bytes) ----------------
// z f16: 4 slices x [128 rows x 64 f16] = 65536 ; w ring: 2 x 16384 = 32768
#define ZH_OFF    0u
#define W_OFF     65536u
#define SMEM_BYTES 98304u

// ---------------------------------------------------------------------------
// Kernel A: codebook -> f16 (scaled by 4096), fp32 norms, zero accumulators.
// ---------------------------------------------------------------------------
__global__ void conv_w(const float* __restrict__ cb) {
    int r = blockIdx.x * 8 + (threadIdx.x >> 5);
    int lane = threadIdx.x & 31;
    const float* wr = cb + (size_t)r * DD + lane * 8;
    float4 a = *(const float4*)wr;
    float4 b = *(const float4*)(wr + 4);
    float s = a.x * a.x + a.y * a.y + a.z * a.z + a.w * a.w +
              b.x * b.x + b.y * b.y + b.z * b.z + b.w * b.w;
    const float sc = 4096.f;
    __half2 h0 = __float22half2_rn(make_float2(a.x * sc, a.y * sc));
    __half2 h1 = __float22half2_rn(make_float2(a.z * sc, a.w * sc));
    __half2 h2 = __float22half2_rn(make_float2(b.x * sc, b.y * sc));
    __half2 h3 = __float22half2_rn(make_float2(b.z * sc, b.w * sc));
    uint4 pk;
    pk.x = *(uint32_t*)&h0; pk.y = *(uint32_t*)&h1;
    pk.z = *(uint32_t*)&h2; pk.w = *(uint32_t*)&h3;
    *(uint4*)(g_w16 + (size_t)r * DD + lane * 8) = pk;
    #pragma unroll
    for (int o = 16; o > 0; o >>= 1) s += __shfl_xor_sync(0xffffffffu, s, o);
    if (lane == 0) { g_wsq[r] = s; g_counts[r] = 0u; }
    if (r == 0 && lane == 0) { g_loss = 0.0; g_done = 0u; }
}

// ---------------------------------------------------------------------------
// w-slice loader: slice j = (chunk j>>2, dslice j&3): 128 codes x 64 dims f16.
// ---------------------------------------------------------------------------
__device__ __forceinline__ void load_wslice(int j, int bufj, uint32_t sb, int tid) {
    const int ch = j >> 2, s = j & 3;
    const uint32_t base = sb + W_OFF + (uint32_t)bufj * 16384u;
    #pragma unroll
    for (int i = 0; i < 4; ++i) {
        int flat = i * 256 + tid;        // 1024 16B-chunks
        int n = flat >> 3, c = flat & 7;
        uint32_t off = swz((uint32_t)(n * 128 + c * 16));
        cp16(base + off, g_w16 + (size_t)(ch * 128 + n) * DD + s * 64 + c * 8);
    }
}

// ---------------------------------------------------------------------------
// Pass 1: f16 mma (f16 accum) GEMM; per-thread top-3 candidate pool.
// 8 warps = 4(M) x 2(N), warp tile 32x64, 2 CTAs/SM.  (round-7 proven path)
// ---------------------------------------------------------------------------
__global__ void __launch_bounds__(256, 2)
vq_pass1(const float* __restrict__ z) {
    extern __shared__ __align__(1024) char smem[];
    const uint32_t sb = smem_u32(smem);
    const int tid = threadIdx.x;
    const int lane = tid & 31;
    const int warp = tid >> 5;
    const int wm = warp >> 1;        // 0..3 (M)
    const int wn = warp & 1;         // 0..1 (N)
    const int g = lane >> 3;
    const int l7 = lane & 7;
    const int row0 = blockIdx.x * 128;

    // prefetch w slices 0,1
    load_wslice(0, 0, sb, tid); cp_commit();
    load_wslice(1, 1, sb, tid); cp_commit();

    // ---- stage z fp32 -> f16 into smem (fused conversion) ----
    #pragma unroll
    for (int i = 0; i < 32; ++i) {
        int flat = i * 256 + tid;            // 8192 float4
        int r = flat >> 6, d4 = flat & 63;
        float4 v = *(const float4*)(z + (size_t)(row0 + r) * DD + d4 * 4);
        __half2 p0 = __float22half2_rn(make_float2(v.x, v.y));
        __half2 p1 = __float22half2_rn(make_float2(v.z, v.w));
        uint2 pk;
        pk.x = *(uint32_t*)&p0; pk.y = *(uint32_t*)&p1;
        uint32_t off = swz((uint32_t)((d4 >> 4) * 16384 + r * 128 + (d4 & 15) * 8));
        *(uint2*)(smem + ZH_OFF + off) = pk;
    }

    float b0v[4], b1v[4], b2v[4];
    int   b0i[4], b1i[4], b2i[4];
    #pragma unroll
    for (int i = 0; i < 4; ++i) {
        b0v[i] = -FLT_MAX; b1v[i] = -FLT_MAX; b2v[i] = -FLT_MAX;
        b0i[i] = 0; b1i[i] = 0; b2i[i] = 0;
    }

    uint32_t acc[2][8][2];   // f16x2 accumulators

    for (int idx = 0; idx < 128; ++idx) {
        const int ch = idx >> 2, s = idx & 3, buf = idx & 1;

        cp_wait<1>();
        __syncthreads();

        if (s == 0) {
            #pragma unroll
            for (int mf = 0; mf < 2; ++mf)
                #pragma unroll
                for (int nf = 0; nf < 8; ++nf) {
                    acc[mf][nf][0] = 0u; acc[mf][nf][1] = 0u;
                }
        }

        const uint32_t wbase = sb + W_OFF + (uint32_t)buf * 16384u;
        #pragma unroll
        for (int ks = 0; ks < 4; ++ks) {
            uint32_t ah[2][4];
            #pragma unroll
            for (int mf = 0; mf < 2; ++mf) {
                uint32_t off = (uint32_t)((wm * 32 + mf * 16 + (g & 1) * 8 + l7) * 128
                                          + ks * 32 + ((g >> 1) << 4));
                ldsm4(ah[mf], sb + ZH_OFF + swz(off) + (uint32_t)(s * 16384));
            }
            uint32_t bh[4][4];
            #pragma unroll
            for (int p = 0; p < 4; ++p) {
                uint32_t off = (uint32_t)((wn * 64 + p * 16 + ((g >> 1) << 3) + l7) * 128
                                          + ks * 32 + ((g & 1) << 4));
                ldsm4(bh[p], wbase + swz(off));
            }
            #pragma unroll
            for (int mf = 0; mf < 2; ++mf)
                #pragma unroll
                for (int p = 0; p < 4; ++p) {
                    mma16816h(acc[mf][2 * p],     ah[mf], &bh[p][0]);
                    mma16816h(acc[mf][2 * p + 1], ah[mf], &bh[p][2]);
                }
        }

        __syncthreads();
        if (idx + 2 < 128) load_wslice(idx + 2, buf, sb, tid);
        cp_commit();

        if (s == 3) {
            // per-(thread,row-slot) top-3 by scaled dot (bigger = closer)
            #pragma unroll
            for (int nf = 0; nf < 8; ++nf) {
                int col0 = ch * 128 + wn * 64 + nf * 8 + (lane & 3) * 2;
                #pragma unroll
                for (int mf = 0; mf < 2; ++mf) {
                    float2 p01 = __half22float2(*(__half2*)&acc[mf][nf][0]);
                    float2 p23 = __half22float2(*(__half2*)&acc[mf][nf][1]);
                    float vq[4] = {p01.x, p01.y, p23.x, p23.y};
                    #pragma unroll
                    for (int q = 0; q < 4; ++q) {
                        int sl = mf * 2 + (q >> 1);
                        float v = vq[q];
                        int c = col0 + (q & 1);
                        if (v > b2v[sl]) {
                            if (v > b1v[sl]) {
                                b2v[sl] = b1v[sl]; b2i[sl] = b1i[sl];
                                if (v > b0v[sl]) {
                                    b1v[sl] = b0v[sl]; b1i[sl] = b0i[sl];
                                    b0v[sl] = v;       b0i[sl] = c;
                                } else { b1v[sl] = v; b1i[sl] = c; }
                            } else { b2v[sl] = v; b2i[sl] = c; }
                        }
                    }
                }
            }
        }
    }

    // write 3 candidates per (thread, row-slot) -> 24 per row
    #pragma unroll
    for (int sl = 0; sl < 4; ++sl) {
        int r = row0 + wm * 32 + (sl >> 1) * 16 + (sl & 1) * 8 + (lane >> 2);
        int base = r * NPOOL + (wn * 4 + (lane & 3)) * 3;
        g_cval[base]     = b0v[sl]; g_cidx[base]     = b0i[sl];
        g_cval[base + 1] = b1v[sl]; g_cidx[base + 1] = b1i[sl];
        g_cval[base + 2] = b2v[sl]; g_cidx[base + 2] = b2i[sl];
    }
}

// ---------------------------------------------------------------------------
// Pass 2 (fused output + final): per row, exact fp32 rescore of the top-8
// pool candidates with reference rounding fl(fl(zsq+wsq) - 2*dot) and
// first-index tie-break; write z_q, index, histogram, loss. Last block
// computes the loss/perplexity scalars.  (round-8 proven path)
// NOTE: dot/zsq summation orders identical to rounds 3-8 (proven vs reference).
// ---------------------------------------------------------------------------
__global__ void __launch_bounds__(256)
vq_rescore(const float* __restrict__ z, const float* __restrict__ cb,
           float* __restrict__ out, int out_size) {
    const int lane = threadIdx.x & 31;
    const int row = blockIdx.x * 8 + (threadIdx.x >> 5);

    // z row: 8 dims per lane
    float zr[8];
    {
        float4 a = *(const float4*)(z + (size_t)row * DD + lane * 8);
        float4 b = *(const float4*)(z + (size_t)row * DD + lane * 8 + 4);
        zr[0] = a.x; zr[1] = a.y; zr[2] = a.z; zr[3] = a.w;
        zr[4] = b.x; zr[5] = b.y; zr[6] = b.z; zr[7] = b.w;
    }
    float zsq = 0.f;
    #pragma unroll
    for (int k = 0; k < 8; ++k) zsq += zr[k] * zr[k];
    #pragma unroll
    for (int o = 16; o > 0; o >>= 1) zsq += __shfl_xor_sync(0xffffffffu, zsq, o);

    // candidate pool
    float cv = -FLT_MAX; int ci = 0x7fffffff;
    if (lane < NPOOL) { cv = g_cval[row * NPOOL + lane]; ci = g_cidx[row * NPOOL + lane]; }

    // select top-8 candidates by approx dot (shfl only)
    int cand[8];
    #pragma unroll
    for (int t = 0; t < 8; ++t) {
        float m = cv; int mi = ci;
        #pragma unroll
        for (int o = 16; o > 0; o >>= 1) {
            float mv = __shfl_xor_sync(0xffffffffu, m, o);
            int   mj = __shfl_xor_sync(0xffffffffu, mi, o);
            if (mv > m || (mv == m && mj < mi)) { m = mv; mi = mj; }
        }
        cand[t] = mi;
        if (ci == mi) cv = -FLT_MAX;
    }

    // prefetch all 8 candidate rows (MLP=16)
    float4 wa[8], wb[8];
    #pragma unroll
    for (int t = 0; t < 8; ++t) {
        const float* wp = cb + (size_t)cand[t] * DD + lane * 8;
        wa[t] = *(const float4*)wp;
        wb[t] = *(const float4*)(wp + 4);
    }

    // exact fp32 partial dots (same fma order as prior rounds)
    float dp[8];
    #pragma unroll
    for (int t = 0; t < 8; ++t) {
        float d = 0.f;
        d = fmaf(zr[0], wa[t].x, d); d = fmaf(zr[1], wa[t].y, d);
        d = fmaf(zr[2], wa[t].z, d); d = fmaf(zr[3], wa[t].w, d);
        d = fmaf(zr[4], wb[t].x, d); d = fmaf(zr[5], wb[t].y, d);
        d = fmaf(zr[6], wb[t].z, d); d = fmaf(zr[7], wb[t].w, d);
        dp[t] = d;
    }
    #pragma unroll
    for (int o = 16; o > 0; o >>= 1) {
        #pragma unroll
        for (int t = 0; t < 8; ++t)
            dp[t] += __shfl_xor_sync(0xffffffffu, dp[t], o);
    }

    float bdist = FLT_MAX;
    int   widx = 0x7fffffff;
    #pragma unroll
    for (int t = 0; t < 8; ++t) {
        float dist = (zsq + __ldg(&g_wsq[cand[t]])) - 2.f * dp[t];
        if (dist < bdist || (dist == bdist && cand[t] < widx)) {
            bdist = dist; widx = cand[t];
        }
    }

    // outputs: gather winner row (L2 hit)
    const float* wp = cb + (size_t)widx * DD + lane * 8;
    float4 a = *(const float4*)wp;
    float4 b = *(const float4*)(wp + 4);
    float lsum = 0.f;
    {
        float* op = out + (size_t)row * DD + lane * 8;
        if ((row + 1) * DD <= out_size) {
            *(float4*)op = a;
            *(float4*)(op + 4) = b;
        }
        float w8[8] = {a.x, a.y, a.z, a.w, b.x, b.y, b.z, b.w};
        #pragma unroll
        for (int k = 0; k < 8; ++k) {
            float dd = w8[k] - zr[k];
            lsum += dd * dd;
        }
    }
    #pragma unroll
    for (int o = 16; o > 0; o >>= 1) lsum += __shfl_xor_sync(0xffffffffu, lsum, o);

    if (lane == 0) {
        atomicAdd(&g_counts[widx], 1u);
        atomicAdd(&g_loss, (double)lsum);
        int pos = BB * DD + row;
        if (pos < out_size) out[pos] = (float)widx;
        __threadfence();
    }

    // ---- fused finalization: last block computes scalars ----
    __shared__ int slast;
    __shared__ double red[8];
    __syncthreads();
    if (threadIdx.x == 0)
        slast = (atomicAdd(&g_done, 1u) == (unsigned)(gridDim.x - 1)) ? 1 : 0;
    __syncthreads();
    if (slast) {
        int t = threadIdx.x;
        double s = 0.0;
        for (int k = t; k < KK; k += 256) {
            unsigned c = atomicAdd(&g_counts[k], 0u);   // coherent read
            float p = (float)c / (float)BB;
            s += (double)(p * logf(p + 1e-10f));
        }
        #pragma unroll
        for (int o = 16; o > 0; o >>= 1) s += __shfl_xor_sync(0xffffffffu, s, o);
        if ((t & 31) == 0) red[t >> 5] = s;
        __syncthreads();
        if (t < 32) {
            double v = (t < 8) ? red[t] : 0.0;
            #pragma unroll
            for (int o = 4; o > 0; o >>= 1) v += __shfl_xor_sync(0xffffffffu, v, o);
            if (t == 0) {
                double loss = atomicAdd(&g_loss, 0.0);  // coherent read
                int p0 = BB * DD + BB;
                if (p0 < out_size)
                    out[p0] = (float)(loss / ((double)BB * (double)DD) * 1.25);
                if (p0 + 1 < out_size)
                    out[p0 + 1] = expf((float)(-v));
            }
        }
    }
}

// ---------------------------------------------------------------------------
extern "C" void kernel_launch(void* const* d_in, const int* in_sizes, int n_in,
                              void* d_out, int out_size) {
    const float* z  = (const float*)d_in[0];   // z_e [32768, 256] f32
    const float* cb = (const float*)d_in[1];   // codebook [4096, 256] f32
    float* out = (float*)d_out;

    cudaFuncSetAttribute(vq_pass1,
                         cudaFuncAttributeMaxDynamicSharedMemorySize, SMEM_BYTES);

    conv_w<<<KK / 8, 256>>>(cb);
    vq_pass1<<<BB / 128, 256, SMEM_BYTES>>>(z);
    vq_rescore<<<BB / 8, 256>>>(z, cb, out, out_size);
}

// round 10
// speedup vs baseline: 1.9254x; 1.0774x over previous
#include <cuda_runtime.h>
#include <cuda_fp16.h>
#include <math.h>
#include <float.h>
#include <stdint.h>

#define BB 32768
#define DD 256
#define KK 4096
#define GRID1 296          // 2 CTAs x 148 SMs, single wave
#define NUNITS 2048        // 256 row-blocks x 8 chunk-groups
#define POOLW 128          // per-row pool: 8 cg x 8 threads x top-2

// ---- scratch (static device globals: allocation-free) ----
__device__ float          g_wsq[KK];
__device__ unsigned int   g_counts[KK];
__device__ double         g_loss;
__device__ unsigned int   g_done;
__device__ __half         g_w16[KK * DD];        // f16(w * 4096)
__device__ float          g_cval[BB * POOLW];
__device__ int            g_cidx[BB * POOLW];

// ---------------- helpers ----------------
__device__ __forceinline__ uint32_t smem_u32(const void* p) {
    return (uint32_t)__cvta_generic_to_shared(p);
}
__device__ __forceinline__ void cp16(uint32_t dst, const void* src) {
    asm volatile("cp.async.cg.shared.global [%0], [%1], 16;" :: "r"(dst), "l"(src));
}
__device__ __forceinline__ void cp_commit() {
    asm volatile("cp.async.commit_group;" ::: "memory");
}
template <int N> __device__ __forceinline__ void cp_wait() {
    asm volatile("cp.async.wait_group %0;" :: "n"(N) : "memory");
}
__device__ __forceinline__ uint32_t swz(uint32_t off) {
    return off ^ ((off >> 3) & 0x70);
}
__device__ __forceinline__ void ldsm4(uint32_t* r, uint32_t addr) {
    asm volatile("ldmatrix.sync.aligned.m8n8.x4.shared.b16 {%0,%1,%2,%3}, [%4];"
                 : "=r"(r[0]), "=r"(r[1]), "=r"(r[2]), "=r"(r[3]) : "r"(addr));
}
// f16 inputs, f16 accumulators (2 regs)
__device__ __forceinline__ void mma16816h(uint32_t* c, const uint32_t* a,
                                          const uint32_t* b) {
    asm volatile(
        "mma.sync.aligned.m16n8k16.row.col.f16.f16.f16.f16 "
        "{%0,%1}, {%2,%3,%4,%5}, {%6,%7}, {%0,%1};"
        : "+r"(c[0]), "+r"(c[1])
        : "r"(a[0]), "r"(a[1]), "r"(a[2]), "r"(a[3]), "r"(b[0]), "r"(b[1]));
}

// ---------------- pass-1 smem layout (bytes) ----------------
// z f16: 4 slices x [128 rows x 64 f16] = 65536 ; w ring: 2 x 16384 = 32768
#define ZH_OFF    0u
#define W_OFF     65536u
#define SMEM_BYTES 98304u

// ---------------------------------------------------------------------------
// Kernel A: codebook -> f16 (scaled by 4096), fp32 norms, zero accumulators.
// ---------------------------------------------------------------------------
__global__ void conv_w(const float* __restrict__ cb) {
    int r = blockIdx.x * 8 + (threadIdx.x >> 5);
    int lane = threadIdx.x & 31;
    const float* wr = cb + (size_t)r * DD + lane * 8;
    float4 a = *(const float4*)wr;
    float4 b = *(const float4*)(wr + 4);
    float s = a.x * a.x + a.y * a.y + a.z * a.z + a.w * a.w +
              b.x * b.x + b.y * b.y + b.z * b.z + b.w * b.w;
    const float sc = 4096.f;
    __half2 h0 = __float22half2_rn(make_float2(a.x * sc, a.y * sc));
    __half2 h1 = __float22half2_rn(make_float2(a.z * sc, a.w * sc));
    __half2 h2 = __float22half2_rn(make_float2(b.x * sc, b.y * sc));
    __half2 h3 = __float22half2_rn(make_float2(b.z * sc, b.w * sc));
    uint4 pk;
    pk.x = *(uint32_t*)&h0; pk.y = *(uint32_t*)&h1;
    pk.z = *(uint32_t*)&h2; pk.w = *(uint32_t*)&h3;
    *(uint4*)(g_w16 + (size_t)r * DD + lane * 8) = pk;
    #pragma unroll
    for (int o = 16; o > 0; o >>= 1) s += __shfl_xor_sync(0xffffffffu, s, o);
    if (lane == 0) { g_wsq[r] = s; g_counts[r] = 0u; }
    if (r == 0 && lane == 0) { g_loss = 0.0; g_done = 0u; }
}

// ---------------------------------------------------------------------------
// w-slice loader for absolute slice a: ch=(a>>2)&31, s=a&3, ring buf=a&1.
// ---------------------------------------------------------------------------
__device__ __forceinline__ void load_wslice(int a, uint32_t sb, int tid) {
    const int ch = (a >> 2) & 31, s = a & 3;
    const uint32_t base = sb + W_OFF + (uint32_t)((a & 1) * 16384);
    #pragma unroll
    for (int i = 0; i < 4; ++i) {
        int flat = i * 256 + tid;        // 1024 16B-chunks
        int n = flat >> 3, c = flat & 7;
        uint32_t off = swz((uint32_t)(n * 128 + c * 16));
        cp16(base + off, g_w16 + (size_t)(ch * 128 + n) * DD + s * 64 + c * 8);
    }
}

// ---------------------------------------------------------------------------
// z staging: rows [row0, row0+128) fp32 -> f16 swizzled smem (plain stores).
// ---------------------------------------------------------------------------
__device__ __forceinline__ void stage_z(const float* __restrict__ z, int row0,
                                        char* smem, int tid) {
    #pragma unroll
    for (int i = 0; i < 32; ++i) {
        int flat = i * 256 + tid;            // 8192 float4
        int r = flat >> 6, d4 = flat & 63;
        float4 v = *(const float4*)(z + (size_t)(row0 + r) * DD + d4 * 4);
        __half2 p0 = __float22half2_rn(make_float2(v.x, v.y));
        __half2 p1 = __float22half2_rn(make_float2(v.z, v.w));
        uint2 pk;
        pk.x = *(uint32_t*)&p0; pk.y = *(uint32_t*)&p1;
        uint32_t off = swz((uint32_t)((d4 >> 4) * 16384 + r * 128 + (d4 & 15) * 8));
        *(uint2*)(smem + ZH_OFF + off) = pk;
    }
}

// ---------------------------------------------------------------------------
// Pass 1 (balanced): 296 CTAs, static contiguous ranges over 2048 units
// (unit = row-block x 4-chunk group). Inner structure identical to round 7;
// per-(thread, chunk-group) top-2 pools (cells of 64 codes).
// ---------------------------------------------------------------------------
__global__ void __launch_bounds__(256, 2)
vq_pass1(const float* __restrict__ z) {
    extern __shared__ __align__(1024) char smem[];
    const uint32_t sb = smem_u32(smem);
    const int tid = threadIdx.x;
    const int lane = tid & 31;
    const int warp = tid >> 5;
    const int wm = warp >> 1;        // 0..3 (M)
    const int wn = warp & 1;         // 0..1 (N)
    const int g = lane >> 3;
    const int l7 = lane & 7;

    // static unit range: [cta*256/37, (cta+1)*256/37) ; 296*256 = 37*2048
    const int u0 = (blockIdx.x * 256) / 37;
    const int u1 = ((blockIdx.x + 1) * 256) / 37;
    const int A0 = u0 * 16, A1 = u1 * 16;    // absolute slice indices

    // prefetch w slices A0, A0+1
    load_wslice(A0, sb, tid); cp_commit();
    load_wslice(A0 + 1, sb, tid); cp_commit();

    int cur_rb = -1;
    int row0 = 0;

    float b0v[4], b1v[4];
    int   b0i[4], b1i[4];
    #pragma unroll
    for (int i = 0; i < 4; ++i) {
        b0v[i] = -FLT_MAX; b1v[i] = -FLT_MAX; b0i[i] = 0; b1i[i] = 0;
    }

    uint32_t acc[2][8][2];   // f16x2 accumulators

    for (int a = A0; a < A1; ++a) {
        const int rb = a >> 7, ch = (a >> 2) & 31, s = a & 3, buf = a & 1;

        if (rb != cur_rb) {              // new row-block: restage z
            __syncthreads();             // prior ldsm readers done
            cur_rb = rb;
            row0 = rb * 128;
            stage_z(z, row0, smem, tid);
        }

        cp_wait<1>();
        __syncthreads();

        if (s == 0) {
            #pragma unroll
            for (int mf = 0; mf < 2; ++mf)
                #pragma unroll
                for (int nf = 0; nf < 8; ++nf) {
                    acc[mf][nf][0] = 0u; acc[mf][nf][1] = 0u;
                }
        }

        const uint32_t wbase = sb + W_OFF + (uint32_t)(buf * 16384);
        #pragma unroll
        for (int ks = 0; ks < 4; ++ks) {
            uint32_t ah[2][4];
            #pragma unroll
            for (int mf = 0; mf < 2; ++mf) {
                uint32_t off = (uint32_t)((wm * 32 + mf * 16 + (g & 1) * 8 + l7) * 128
                                          + ks * 32 + ((g >> 1) << 4));
                ldsm4(ah[mf], sb + ZH_OFF + swz(off) + (uint32_t)(s * 16384));
            }
            uint32_t bh[4][4];
            #pragma unroll
            for (int p = 0; p < 4; ++p) {
                uint32_t off = (uint32_t)((wn * 64 + p * 16 + ((g >> 1) << 3) + l7) * 128
                                          + ks * 32 + ((g & 1) << 4));
                ldsm4(bh[p], wbase + swz(off));
            }
            #pragma unroll
            for (int mf = 0; mf < 2; ++mf)
                #pragma unroll
                for (int p = 0; p < 4; ++p) {
                    mma16816h(acc[mf][2 * p],     ah[mf], &bh[p][0]);
                    mma16816h(acc[mf][2 * p + 1], ah[mf], &bh[p][2]);
                }
        }

        __syncthreads();
        if (a + 2 < A1) load_wslice(a + 2, sb, tid);
        cp_commit();

        if (s == 3) {
            // update per-(thread,row-slot) top-2 over this chunk-group cell
            #pragma unroll
            for (int nf = 0; nf < 8; ++nf) {
                int col0 = ch * 128 + wn * 64 + nf * 8 + (lane & 3) * 2;
                #pragma unroll
                for (int mf = 0; mf < 2; ++mf) {
                    float2 p01 = __half22float2(*(__half2*)&acc[mf][nf][0]);
                    float2 p23 = __half22float2(*(__half2*)&acc[mf][nf][1]);
                    float vq[4] = {p01.x, p01.y, p23.x, p23.y};
                    #pragma unroll
                    for (int q = 0; q < 4; ++q) {
                        int sl = mf * 2 + (q >> 1);
                        float v = vq[q];
                        int c = col0 + (q & 1);
                        if (v > b1v[sl]) {
                            if (v > b0v[sl]) {
                                b1v[sl] = b0v[sl]; b1i[sl] = b0i[sl];
                                b0v[sl] = v;       b0i[sl] = c;
                            } else { b1v[sl] = v; b1i[sl] = c; }
                        }
                    }
                }
            }
            if ((a & 15) == 15) {
                // flush chunk-group pool: 2 entries per (thread,row-slot)
                int cg = (a >> 4) & 7;
                #pragma unroll
                for (int sl = 0; sl < 4; ++sl) {
                    int r = row0 + wm * 32 + (sl >> 1) * 16 + (sl & 1) * 8
                            + (lane >> 2);
                    int base = r * POOLW + cg * 16 + (wn * 4 + (lane & 3)) * 2;
                    g_cval[base]     = b0v[sl]; g_cidx[base]     = b0i[sl];
                    g_cval[base + 1] = b1v[sl]; g_cidx[base + 1] = b1i[sl];
                    b0v[sl] = -FLT_MAX; b1v[sl] = -FLT_MAX;
                    b0i[sl] = 0; b1i[sl] = 0;
                }
            }
        }
    }
}

// ---------------------------------------------------------------------------
// Pass 2 (fused output + final): per row, top-8 by approx from the 128-pool,
// exact fp32 rescore with reference rounding fl(fl(zsq+wsq) - 2*dot) and
// first-index tie-break; write z_q, index, histogram, loss; last block
// computes scalars.  (exact-rescore numerics identical to rounds 3-9)
// ---------------------------------------------------------------------------
__global__ void __launch_bounds__(256)
vq_rescore(const float* __restrict__ z, const float* __restrict__ cb,
           float* __restrict__ out, int out_size) {
    const int lane = threadIdx.x & 31;
    const int row = blockIdx.x * 8 + (threadIdx.x >> 5);

    // z row: 8 dims per lane
    float zr[8];
    {
        float4 a = *(const float4*)(z + (size_t)row * DD + lane * 8);
        float4 b = *(const float4*)(z + (size_t)row * DD + lane * 8 + 4);
        zr[0] = a.x; zr[1] = a.y; zr[2] = a.z; zr[3] = a.w;
        zr[4] = b.x; zr[5] = b.y; zr[6] = b.z; zr[7] = b.w;
    }
    float zsq = 0.f;
    #pragma unroll
    for (int k = 0; k < 8; ++k) zsq += zr[k] * zr[k];
    #pragma unroll
    for (int o = 16; o > 0; o >>= 1) zsq += __shfl_xor_sync(0xffffffffu, zsq, o);

    // pool: 4 entries per lane (code indices unique per row)
    float v[4]; int id[4];
    {
        int base = row * POOLW + lane * 4;
        float4 fv = *(const float4*)(g_cval + base);
        int4   iv = *(const int4*)(g_cidx + base);
        v[0] = fv.x; v[1] = fv.y; v[2] = fv.z; v[3] = fv.w;
        id[0] = iv.x; id[1] = iv.y; id[2] = iv.z; id[3] = iv.w;
    }

    // select top-8 candidates by approx dot
    unsigned cons = 0u;
    int cand[8];
    #pragma unroll
    for (int t = 0; t < 8; ++t) {
        float m = -FLT_MAX; int mi = 0x7fffffff;
        #pragma unroll
        for (int j = 0; j < 4; ++j) {
            if (!((cons >> j) & 1u) &&
                (v[j] > m || (v[j] == m && id[j] < mi))) { m = v[j]; mi = id[j]; }
        }
        #pragma unroll
        for (int o = 16; o > 0; o >>= 1) {
            float mv = __shfl_xor_sync(0xffffffffu, m, o);
            int   mj = __shfl_xor_sync(0xffffffffu, mi, o);
            if (mv > m || (mv == m && mj < mi)) { m = mv; mi = mj; }
        }
        cand[t] = mi;
        #pragma unroll
        for (int j = 0; j < 4; ++j)
            if (id[j] == mi) cons |= 1u << j;
    }

    // prefetch all 8 candidate rows (MLP=16)
    float4 wa[8], wb[8];
    #pragma unroll
    for (int t = 0; t < 8; ++t) {
        const float* wp = cb + (size_t)cand[t] * DD + lane * 8;
        wa[t] = *(const float4*)wp;
        wb[t] = *(const float4*)(wp + 4);
    }

    // exact fp32 partial dots (same fma order as prior rounds)
    float dp[8];
    #pragma unroll
    for (int t = 0; t < 8; ++t) {
        float d = 0.f;
        d = fmaf(zr[0], wa[t].x, d); d = fmaf(zr[1], wa[t].y, d);
        d = fmaf(zr[2], wa[t].z, d); d = fmaf(zr[3], wa[t].w, d);
        d = fmaf(zr[4], wb[t].x, d); d = fmaf(zr[5], wb[t].y, d);
        d = fmaf(zr[6], wb[t].z, d); d = fmaf(zr[7], wb[t].w, d);
        dp[t] = d;
    }
    #pragma unroll
    for (int o = 16; o > 0; o >>= 1) {
        #pragma unroll
        for (int t = 0; t < 8; ++t)
            dp[t] += __shfl_xor_sync(0xffffffffu, dp[t], o);
    }

    float bdist = FLT_MAX;
    int   widx = 0x7fffffff;
    #pragma unroll
    for (int t = 0; t < 8; ++t) {
        float dist = (zsq + __ldg(&g_wsq[cand[t]])) - 2.f * dp[t];
        if (dist < bdist || (dist == bdist && cand[t] < widx)) {
            bdist = dist; widx = cand[t];
        }
    }

    // outputs: gather winner row (L2 hit)
    const float* wp = cb + (size_t)widx * DD + lane * 8;
    float4 a = *(const float4*)wp;
    float4 b = *(const float4*)(wp + 4);
    float lsum = 0.f;
    {
        float* op = out + (size_t)row * DD + lane * 8;
        if ((row + 1) * DD <= out_size) {
            *(float4*)op = a;
            *(float4*)(op + 4) = b;
        }
        float w8[8] = {a.x, a.y, a.z, a.w, b.x, b.y, b.z, b.w};
        #pragma unroll
        for (int k = 0; k < 8; ++k) {
            float dd = w8[k] - zr[k];
            lsum += dd * dd;
        }
    }
    #pragma unroll
    for (int o = 16; o > 0; o >>= 1) lsum += __shfl_xor_sync(0xffffffffu, lsum, o);

    if (lane == 0) {
        atomicAdd(&g_counts[widx], 1u);
        atomicAdd(&g_loss, (double)lsum);
        int pos = BB * DD + row;
        if (pos < out_size) out[pos] = (float)widx;
        __threadfence();
    }

    // ---- fused finalization: last block computes scalars ----
    __shared__ int slast;
    __shared__ double red[8];
    __syncthreads();
    if (threadIdx.x == 0)
        slast = (atomicAdd(&g_done, 1u) == (unsigned)(gridDim.x - 1)) ? 1 : 0;
    __syncthreads();
    if (slast) {
        int t = threadIdx.x;
        double s = 0.0;
        for (int k = t; k < KK; k += 256) {
            unsigned c = atomicAdd(&g_counts[k], 0u);   // coherent read
            float p = (float)c / (float)BB;
            s += (double)(p * logf(p + 1e-10f));
        }
        #pragma unroll
        for (int o = 16; o > 0; o >>= 1) s += __shfl_xor_sync(0xffffffffu, s, o);
        if ((t & 31) == 0) red[t >> 5] = s;
        __syncthreads();
        if (t < 32) {
            double vv = (t < 8) ? red[t] : 0.0;
            #pragma unroll
            for (int o = 4; o > 0; o >>= 1) vv += __shfl_xor_sync(0xffffffffu, vv, o);
            if (t == 0) {
                double loss = atomicAdd(&g_loss, 0.0);  // coherent read
                int p0 = BB * DD + BB;
                if (p0 < out_size)
                    out[p0] = (float)(loss / ((double)BB * (double)DD) * 1.25);
                if (p0 + 1 < out_size)
                    out[p0 + 1] = expf((float)(-vv));
            }
        }
    }
}

// ---------------------------------------------------------------------------
extern "C" void kernel_launch(void* const* d_in, const int* in_sizes, int n_in,
                              void* d_out, int out_size) {
    const float* z  = (const float*)d_in[0];   // z_e [32768, 256] f32
    const float* cb = (const float*)d_in[1];   // codebook [4096, 256] f32
    float* out = (float*)d_out;

    cudaFuncSetAttribute(vq_pass1,
                         cudaFuncAttributeMaxDynamicSharedMemorySize, SMEM_BYTES);

    conv_w<<<KK / 8, 256>>>(cb);
    vq_pass1<<<GRID1, 256, SMEM_BYTES>>>(z);
    vq_rescore<<<BB / 8, 256>>>(z, cb, out, out_size);
}

// round 11
// speedup vs baseline: 1.9486x; 1.0120x over previous
#include <cuda_runtime.h>
#include <cuda_fp16.h>
#include <math.h>
#include <float.h>
#include <stdint.h>

#define BB 32768
#define DD 256
#define KK 4096
#define GRID1 296          // 2 CTAs x 148 SMs, single wave
#define POOLW 128          // per-row pool: 8 cg x 8 threads x top-2

// ---- scratch (static device globals: allocation-free) ----
__device__ float          g_wsq[KK];
__device__ unsigned int   g_counts[KK];
__device__ double         g_loss;
__device__ unsigned int   g_done;
__device__ __half         g_w16[KK * DD];        // f16(w * 4096)
__device__ float          g_cval[BB * POOLW];
__device__ int            g_cidx[BB * POOLW];

// ---------------- helpers ----------------
__device__ __forceinline__ uint32_t smem_u32(const void* p) {
    return (uint32_t)__cvta_generic_to_shared(p);
}
__device__ __forceinline__ void cp16(uint32_t dst, const void* src) {
    asm volatile("cp.async.cg.shared.global [%0], [%1], 16;" :: "r"(dst), "l"(src));
}
__device__ __forceinline__ void cp_commit() {
    asm volatile("cp.async.commit_group;" ::: "memory");
}
template <int N> __device__ __forceinline__ void cp_wait() {
    asm volatile("cp.async.wait_group %0;" :: "n"(N) : "memory");
}
__device__ __forceinline__ uint32_t swz(uint32_t off) {
    return off ^ ((off >> 3) & 0x70);
}
__device__ __forceinline__ void ldsm4(uint32_t* r, uint32_t addr) {
    asm volatile("ldmatrix.sync.aligned.m8n8.x4.shared.b16 {%0,%1,%2,%3}, [%4];"
                 : "=r"(r[0]), "=r"(r[1]), "=r"(r[2]), "=r"(r[3]) : "r"(addr));
}
// f16 inputs, f16 accumulators (2 regs)
__device__ __forceinline__ void mma16816h(uint32_t* c, const uint32_t* a,
                                          const uint32_t* b) {
    asm volatile(
        "mma.sync.aligned.m16n8k16.row.col.f16.f16.f16.f16 "
        "{%0,%1}, {%2,%3,%4,%5}, {%6,%7}, {%0,%1};"
        : "+r"(c[0]), "+r"(c[1])
        : "r"(a[0]), "r"(a[1]), "r"(a[2]), "r"(a[3]), "r"(b[0]), "r"(b[1]));
}

// ---------------- pass-1 smem layout (bytes) ----------------
// z f16: 4 slices x [128 rows x 64 f16] = 65536 ; w ring: 2 x 16384 = 32768
#define ZH_OFF    0u
#define W_OFF     65536u
#define SMEM_BYTES 98304u

// ---------------------------------------------------------------------------
// Kernel A: codebook -> f16 (scaled by 4096), fp32 norms, zero accumulators.
// ---------------------------------------------------------------------------
__global__ void conv_w(const float* __restrict__ cb) {
    int r = blockIdx.x * 8 + (threadIdx.x >> 5);
    int lane = threadIdx.x & 31;
    const float* wr = cb + (size_t)r * DD + lane * 8;
    float4 a = *(const float4*)wr;
    float4 b = *(const float4*)(wr + 4);
    float s = a.x * a.x + a.y * a.y + a.z * a.z + a.w * a.w +
              b.x * b.x + b.y * b.y + b.z * b.z + b.w * b.w;
    const float sc = 4096.f;
    __half2 h0 = __float22half2_rn(make_float2(a.x * sc, a.y * sc));
    __half2 h1 = __float22half2_rn(make_float2(a.z * sc, a.w * sc));
    __half2 h2 = __float22half2_rn(make_float2(b.x * sc, b.y * sc));
    __half2 h3 = __float22half2_rn(make_float2(b.z * sc, b.w * sc));
    uint4 pk;
    pk.x = *(uint32_t*)&h0; pk.y = *(uint32_t*)&h1;
    pk.z = *(uint32_t*)&h2; pk.w = *(uint32_t*)&h3;
    *(uint4*)(g_w16 + (size_t)r * DD + lane * 8) = pk;
    #pragma unroll
    for (int o = 16; o > 0; o >>= 1) s += __shfl_xor_sync(0xffffffffu, s, o);
    if (lane == 0) { g_wsq[r] = s; g_counts[r] = 0u; }
    if (r == 0 && lane == 0) { g_loss = 0.0; g_done = 0u; }
}

// ---------------------------------------------------------------------------
// w-slice loader for absolute slice a: ch=(a>>2)&31, s=a&3, ring buf=a&1.
// ---------------------------------------------------------------------------
__device__ __forceinline__ void load_wslice(int a, uint32_t sb, int tid) {
    const int ch = (a >> 2) & 31, s = a & 3;
    const uint32_t base = sb + W_OFF + (uint32_t)((a & 1) * 16384);
    #pragma unroll
    for (int i = 0; i < 4; ++i) {
        int flat = i * 256 + tid;        // 1024 16B-chunks
        int n = flat >> 3, c = flat & 7;
        uint32_t off = swz((uint32_t)(n * 128 + c * 16));
        cp16(base + off, g_w16 + (size_t)(ch * 128 + n) * DD + s * 64 + c * 8);
    }
}

// ---------------------------------------------------------------------------
// z staging: rows [row0, row0+128) fp32 -> f16 swizzled smem (plain stores).
// ---------------------------------------------------------------------------
__device__ __forceinline__ void stage_z(const float* __restrict__ z, int row0,
                                        char* smem, int tid) {
    #pragma unroll
    for (int i = 0; i < 32; ++i) {
        int flat = i * 256 + tid;            // 8192 float4
        int r = flat >> 6, d4 = flat & 63;
        float4 v = *(const float4*)(z + (size_t)(row0 + r) * DD + d4 * 4);
        __half2 p0 = __float22half2_rn(make_float2(v.x, v.y));
        __half2 p1 = __float22half2_rn(make_float2(v.z, v.w));
        uint2 pk;
        pk.x = *(uint32_t*)&p0; pk.y = *(uint32_t*)&p1;
        uint32_t off = swz((uint32_t)((d4 >> 4) * 16384 + r * 128 + (d4 & 15) * 8));
        *(uint2*)(smem + ZH_OFF + off) = pk;
    }
}

// ---------------------------------------------------------------------------
// Pass 1 (balanced): 296 CTAs, static contiguous ranges over 2048 units
// (unit = row-block x 4-chunk group). Per-(thread, chunk-group) top-2 pools.
// (round-10 proven path, unchanged)
// ---------------------------------------------------------------------------
__global__ void __launch_bounds__(256, 2)
vq_pass1(const float* __restrict__ z) {
    extern __shared__ __align__(1024) char smem[];
    const uint32_t sb = smem_u32(smem);
    const int tid = threadIdx.x;
    const int lane = tid & 31;
    const int warp = tid >> 5;
    const int wm = warp >> 1;        // 0..3 (M)
    const int wn = warp & 1;         // 0..1 (N)
    const int g = lane >> 3;
    const int l7 = lane & 7;

    // static unit range: [cta*256/37, (cta+1)*256/37) ; 296*256 = 37*2048
    const int u0 = (blockIdx.x * 256) / 37;
    const int u1 = ((blockIdx.x + 1) * 256) / 37;
    const int A0 = u0 * 16, A1 = u1 * 16;    // absolute slice indices

    // prefetch w slices A0, A0+1
    load_wslice(A0, sb, tid); cp_commit();
    load_wslice(A0 + 1, sb, tid); cp_commit();

    int cur_rb = -1;
    int row0 = 0;

    float b0v[4], b1v[4];
    int   b0i[4], b1i[4];
    #pragma unroll
    for (int i = 0; i < 4; ++i) {
        b0v[i] = -FLT_MAX; b1v[i] = -FLT_MAX; b0i[i] = 0; b1i[i] = 0;
    }

    uint32_t acc[2][8][2];   // f16x2 accumulators

    for (int a = A0; a < A1; ++a) {
        const int rb = a >> 7, ch = (a >> 2) & 31, s = a & 3, buf = a & 1;

        if (rb != cur_rb) {              // new row-block: restage z
            __syncthreads();             // prior ldsm readers done
            cur_rb = rb;
            row0 = rb * 128;
            stage_z(z, row0, smem, tid);
        }

        cp_wait<1>();
        __syncthreads();

        if (s == 0) {
            #pragma unroll
            for (int mf = 0; mf < 2; ++mf)
                #pragma unroll
                for (int nf = 0; nf < 8; ++nf) {
                    acc[mf][nf][0] = 0u; acc[mf][nf][1] = 0u;
                }
        }

        const uint32_t wbase = sb + W_OFF + (uint32_t)(buf * 16384);
        #pragma unroll
        for (int ks = 0; ks < 4; ++ks) {
            uint32_t ah[2][4];
            #pragma unroll
            for (int mf = 0; mf < 2; ++mf) {
                uint32_t off = (uint32_t)((wm * 32 + mf * 16 + (g & 1) * 8 + l7) * 128
                                          + ks * 32 + ((g >> 1) << 4));
                ldsm4(ah[mf], sb + ZH_OFF + swz(off) + (uint32_t)(s * 16384));
            }
            uint32_t bh[4][4];
            #pragma unroll
            for (int p = 0; p < 4; ++p) {
                uint32_t off = (uint32_t)((wn * 64 + p * 16 + ((g >> 1) << 3) + l7) * 128
                                          + ks * 32 + ((g & 1) << 4));
                ldsm4(bh[p], wbase + swz(off));
            }
            #pragma unroll
            for (int mf = 0; mf < 2; ++mf)
                #pragma unroll
                for (int p = 0; p < 4; ++p) {
                    mma16816h(acc[mf][2 * p],     ah[mf], &bh[p][0]);
                    mma16816h(acc[mf][2 * p + 1], ah[mf], &bh[p][2]);
                }
        }

        __syncthreads();
        if (a + 2 < A1) load_wslice(a + 2, sb, tid);
        cp_commit();

        if (s == 3) {
            // update per-(thread,row-slot) top-2 over this chunk-group cell
            #pragma unroll
            for (int nf = 0; nf < 8; ++nf) {
                int col0 = ch * 128 + wn * 64 + nf * 8 + (lane & 3) * 2;
                #pragma unroll
                for (int mf = 0; mf < 2; ++mf) {
                    float2 p01 = __half22float2(*(__half2*)&acc[mf][nf][0]);
                    float2 p23 = __half22float2(*(__half2*)&acc[mf][nf][1]);
                    float vq[4] = {p01.x, p01.y, p23.x, p23.y};
                    #pragma unroll
                    for (int q = 0; q < 4; ++q) {
                        int sl = mf * 2 + (q >> 1);
                        float v = vq[q];
                        int c = col0 + (q & 1);
                        if (v > b1v[sl]) {
                            if (v > b0v[sl]) {
                                b1v[sl] = b0v[sl]; b1i[sl] = b0i[sl];
                                b0v[sl] = v;       b0i[sl] = c;
                            } else { b1v[sl] = v; b1i[sl] = c; }
                        }
                    }
                }
            }
            if ((a & 15) == 15) {
                // flush chunk-group pool: 2 entries per (thread,row-slot)
                int cg = (a >> 4) & 7;
                #pragma unroll
                for (int sl = 0; sl < 4; ++sl) {
                    int r = row0 + wm * 32 + (sl >> 1) * 16 + (sl & 1) * 8
                            + (lane >> 2);
                    int base = r * POOLW + cg * 16 + (wn * 4 + (lane & 3)) * 2;
                    g_cval[base]     = b0v[sl]; g_cidx[base]     = b0i[sl];
                    g_cval[base + 1] = b1v[sl]; g_cidx[base + 1] = b1i[sl];
                    b0v[sl] = -FLT_MAX; b1v[sl] = -FLT_MAX;
                    b0i[sl] = 0; b1i[sl] = 0;
                }
            }
        }
    }
}

// ---------------------------------------------------------------------------
// Pass 2 (fused output + final): per row, top-4 by approx from the 128-pool,
// exact fp32 rescore with reference rounding fl(fl(zsq+wsq) - 2*dot) and
// first-index tie-break; z_q written from the winner's registers (no
// re-gather). Last block computes scalars.
// NOTE: exact-rescore fma/shfl orders identical to rounds 3-10.
// ---------------------------------------------------------------------------
__global__ void __launch_bounds__(256)
vq_rescore(const float* __restrict__ z, const float* __restrict__ cb,
           float* __restrict__ out, int out_size) {
    const int lane = threadIdx.x & 31;
    const int row = blockIdx.x * 8 + (threadIdx.x >> 5);

    // z row: 8 dims per lane
    float zr[8];
    {
        float4 a = *(const float4*)(z + (size_t)row * DD + lane * 8);
        float4 b = *(const float4*)(z + (size_t)row * DD + lane * 8 + 4);
        zr[0] = a.x; zr[1] = a.y; zr[2] = a.z; zr[3] = a.w;
        zr[4] = b.x; zr[5] = b.y; zr[6] = b.z; zr[7] = b.w;
    }
    float zsq = 0.f;
    #pragma unroll
    for (int k = 0; k < 8; ++k) zsq += zr[k] * zr[k];
    #pragma unroll
    for (int o = 16; o > 0; o >>= 1) zsq += __shfl_xor_sync(0xffffffffu, zsq, o);

    // pool: 4 entries per lane (code indices unique per row)
    float v[4]; int id[4];
    {
        int base = row * POOLW + lane * 4;
        float4 fv = *(const float4*)(g_cval + base);
        int4   iv = *(const int4*)(g_cidx + base);
        v[0] = fv.x; v[1] = fv.y; v[2] = fv.z; v[3] = fv.w;
        id[0] = iv.x; id[1] = iv.y; id[2] = iv.z; id[3] = iv.w;
    }

    // select top-4 candidates by approx dot
    unsigned cons = 0u;
    int cand[4];
    #pragma unroll
    for (int t = 0; t < 4; ++t) {
        float m = -FLT_MAX; int mi = 0x7fffffff;
        #pragma unroll
        for (int j = 0; j < 4; ++j) {
            if (!((cons >> j) & 1u) &&
                (v[j] > m || (v[j] == m && id[j] < mi))) { m = v[j]; mi = id[j]; }
        }
        #pragma unroll
        for (int o = 16; o > 0; o >>= 1) {
            float mv = __shfl_xor_sync(0xffffffffu, m, o);
            int   mj = __shfl_xor_sync(0xffffffffu, mi, o);
            if (mv > m || (mv == m && mj < mi)) { m = mv; mi = mj; }
        }
        cand[t] = mi;
        #pragma unroll
        for (int j = 0; j < 4; ++j)
            if (id[j] == mi) cons |= 1u << j;
    }

    // prefetch all 4 candidate rows (MLP=8)
    float4 wa[4], wb[4];
    #pragma unroll
    for (int t = 0; t < 4; ++t) {
        const float* wp = cb + (size_t)cand[t] * DD + lane * 8;
        wa[t] = *(const float4*)wp;
        wb[t] = *(const float4*)(wp + 4);
    }

    // exact fp32 partial dots (same fma order as prior rounds)
    float dp[4];
    #pragma unroll
    for (int t = 0; t < 4; ++t) {
        float d = 0.f;
        d = fmaf(zr[0], wa[t].x, d); d = fmaf(zr[1], wa[t].y, d);
        d = fmaf(zr[2], wa[t].z, d); d = fmaf(zr[3], wa[t].w, d);
        d = fmaf(zr[4], wb[t].x, d); d = fmaf(zr[5], wb[t].y, d);
        d = fmaf(zr[6], wb[t].z, d); d = fmaf(zr[7], wb[t].w, d);
        dp[t] = d;
    }
    #pragma unroll
    for (int o = 16; o > 0; o >>= 1) {
        #pragma unroll
        for (int t = 0; t < 4; ++t)
            dp[t] += __shfl_xor_sync(0xffffffffu, dp[t], o);
    }

    float bdist = FLT_MAX;
    int   widx = 0x7fffffff;
    #pragma unroll
    for (int t = 0; t < 4; ++t) {
        float dist = (zsq + __ldg(&g_wsq[cand[t]])) - 2.f * dp[t];
        if (dist < bdist || (dist == bdist && cand[t] < widx)) {
            bdist = dist; widx = cand[t];
        }
    }

    // winner row already in registers: select it
    float4 oa = wa[0], ob = wb[0];
    #pragma unroll
    for (int t = 1; t < 4; ++t)
        if (cand[t] == widx) { oa = wa[t]; ob = wb[t]; }

    float lsum = 0.f;
    {
        float* op = out + (size_t)row * DD + lane * 8;
        if ((row + 1) * DD <= out_size) {
            *(float4*)op = oa;
            *(float4*)(op + 4) = ob;
        }
        float w8[8] = {oa.x, oa.y, oa.z, oa.w, ob.x, ob.y, ob.z, ob.w};
        #pragma unroll
        for (int k = 0; k < 8; ++k) {
            float dd = w8[k] - zr[k];
            lsum += dd * dd;
        }
    }
    #pragma unroll
    for (int o = 16; o > 0; o >>= 1) lsum += __shfl_xor_sync(0xffffffffu, lsum, o);

    if (lane == 0) {
        atomicAdd(&g_counts[widx], 1u);
        atomicAdd(&g_loss, (double)lsum);
        int pos = BB * DD + row;
        if (pos < out_size) out[pos] = (float)widx;
        __threadfence();
    }

    // ---- fused finalization: last block computes scalars ----
    __shared__ int slast;
    __shared__ double red[8];
    __syncthreads();
    if (threadIdx.x == 0)
        slast = (atomicAdd(&g_done, 1u) == (unsigned)(gridDim.x - 1)) ? 1 : 0;
    __syncthreads();
    if (slast) {
        int t = threadIdx.x;
        double s = 0.0;
        for (int k = t; k < KK; k += 256) {
            unsigned c = atomicAdd(&g_counts[k], 0u);   // coherent read
            float p = (float)c / (float)BB;
            s += (double)(p * logf(p + 1e-10f));
        }
        #pragma unroll
        for (int o = 16; o > 0; o >>= 1) s += __shfl_xor_sync(0xffffffffu, s, o);
        if ((t & 31) == 0) red[t >> 5] = s;
        __syncthreads();
        if (t < 32) {
            double vv = (t < 8) ? red[t] : 0.0;
            #pragma unroll
            for (int o = 4; o > 0; o >>= 1) vv += __shfl_xor_sync(0xffffffffu, vv, o);
            if (t == 0) {
                double loss = atomicAdd(&g_loss, 0.0);  // coherent read
                int p0 = BB * DD + BB;
                if (p0 < out_size)
                    out[p0] = (float)(loss / ((double)BB * (double)DD) * 1.25);
                if (p0 + 1 < out_size)
                    out[p0 + 1] = expf((float)(-vv));
            }
        }
    }
}

// ---------------------------------------------------------------------------
extern "C" void kernel_launch(void* const* d_in, const int* in_sizes, int n_in,
                              void* d_out, int out_size) {
    const float* z  = (const float*)d_in[0];   // z_e [32768, 256] f32
    const float* cb = (const float*)d_in[1];   // codebook [4096, 256] f32
    float* out = (float*)d_out;

    cudaFuncSetAttribute(vq_pass1,
                         cudaFuncAttributeMaxDynamicSharedMemorySize, SMEM_BYTES);

    conv_w<<<KK / 8, 256>>>(cb);
    vq_pass1<<<GRID1, 256, SMEM_BYTES>>>(z);
    vq_rescore<<<BB / 8, 256>>>(z, cb, out, out_size);
}

// round 12
// speedup vs baseline: 2.0167x; 1.0350x over previous
#include <cuda_runtime.h>
#include <cuda_fp16.h>
#include <math.h>
#include <float.h>
#include <stdint.h>

#define BB 32768
#define DD 256
#define KK 4096
#define GRID1 296          // 2 CTAs x 148 SMs, single wave
#define POOLW 128          // per-row pool: 8 cg x 8 threads x top-2 (packed u32)

// ---- scratch (static device globals: allocation-free) ----
__device__ float          g_wsq[KK];
__device__ unsigned int   g_counts[KK];
__device__ double         g_loss;
__device__ unsigned int   g_done;
__device__ __half         g_w16[KK * DD];        // f16(w * 4096)
__device__ unsigned int   g_pool[BB * POOLW];    // (half val)<<16 | u16 idx

// ---------------- helpers ----------------
__device__ __forceinline__ uint32_t smem_u32(const void* p) {
    return (uint32_t)__cvta_generic_to_shared(p);
}
__device__ __forceinline__ void cp16(uint32_t dst, const void* src) {
    asm volatile("cp.async.cg.shared.global [%0], [%1], 16;" :: "r"(dst), "l"(src));
}
__device__ __forceinline__ void cp_commit() {
    asm volatile("cp.async.commit_group;" ::: "memory");
}
template <int N> __device__ __forceinline__ void cp_wait() {
    asm volatile("cp.async.wait_group %0;" :: "n"(N) : "memory");
}
__device__ __forceinline__ uint32_t swz(uint32_t off) {
    return off ^ ((off >> 3) & 0x70);
}
__device__ __forceinline__ void ldsm4(uint32_t* r, uint32_t addr) {
    asm volatile("ldmatrix.sync.aligned.m8n8.x4.shared.b16 {%0,%1,%2,%3}, [%4];"
                 : "=r"(r[0]), "=r"(r[1]), "=r"(r[2]), "=r"(r[3]) : "r"(addr));
}
// f16 inputs, f16 accumulators (2 regs)
__device__ __forceinline__ void mma16816h(uint32_t* c, const uint32_t* a,
                                          const uint32_t* b) {
    asm volatile(
        "mma.sync.aligned.m16n8k16.row.col.f16.f16.f16.f16 "
        "{%0,%1}, {%2,%3,%4,%5}, {%6,%7}, {%0,%1};"
        : "+r"(c[0]), "+r"(c[1])
        : "r"(a[0]), "r"(a[1]), "r"(a[2]), "r"(a[3]), "r"(b[0]), "r"(b[1]));
}
// pack: value (exact f16) in high 16 bits, code index in low 16
__device__ __forceinline__ uint32_t pack_cv(float v, int idx) {
    return ((uint32_t)__half_as_ushort(__float2half_rn(v)) << 16) |
           (uint32_t)idx;
}

// ---------------- pass-1 smem layout (bytes) ----------------
// z f16: 4 slices x [128 rows x 64 f16] = 65536 ; w ring: 2 x 16384 = 32768
#define ZH_OFF    0u
#define W_OFF     65536u
#define SMEM_BYTES 98304u

// ---------------------------------------------------------------------------
// Kernel A: codebook -> f16 (scaled by 4096), fp32 norms, zero accumulators.
// ---------------------------------------------------------------------------
__global__ void conv_w(const float* __restrict__ cb) {
    int r = blockIdx.x * 8 + (threadIdx.x >> 5);
    int lane = threadIdx.x & 31;
    const float* wr = cb + (size_t)r * DD + lane * 8;
    float4 a = *(const float4*)wr;
    float4 b = *(const float4*)(wr + 4);
    float s = a.x * a.x + a.y * a.y + a.z * a.z + a.w * a.w +
              b.x * b.x + b.y * b.y + b.z * b.z + b.w * b.w;
    const float sc = 4096.f;
    __half2 h0 = __float22half2_rn(make_float2(a.x * sc, a.y * sc));
    __half2 h1 = __float22half2_rn(make_float2(a.z * sc, a.w * sc));
    __half2 h2 = __float22half2_rn(make_float2(b.x * sc, b.y * sc));
    __half2 h3 = __float22half2_rn(make_float2(b.z * sc, b.w * sc));
    uint4 pk;
    pk.x = *(uint32_t*)&h0; pk.y = *(uint32_t*)&h1;
    pk.z = *(uint32_t*)&h2; pk.w = *(uint32_t*)&h3;
    *(uint4*)(g_w16 + (size_t)r * DD + lane * 8) = pk;
    #pragma unroll
    for (int o = 16; o > 0; o >>= 1) s += __shfl_xor_sync(0xffffffffu, s, o);
    if (lane == 0) { g_wsq[r] = s; g_counts[r] = 0u; }
    if (r == 0 && lane == 0) { g_loss = 0.0; g_done = 0u; }
}

// ---------------------------------------------------------------------------
// w-slice loader for absolute slice a: ch=(a>>2)&31, s=a&3, ring buf=a&1.
// ---------------------------------------------------------------------------
__device__ __forceinline__ void load_wslice(int a, uint32_t sb, int tid) {
    const int ch = (a >> 2) & 31, s = a & 3;
    const uint32_t base = sb + W_OFF + (uint32_t)((a & 1) * 16384);
    #pragma unroll
    for (int i = 0; i < 4; ++i) {
        int flat = i * 256 + tid;        // 1024 16B-chunks
        int n = flat >> 3, c = flat & 7;
        uint32_t off = swz((uint32_t)(n * 128 + c * 16));
        cp16(base + off, g_w16 + (size_t)(ch * 128 + n) * DD + s * 64 + c * 8);
    }
}

// ---------------------------------------------------------------------------
// z staging: rows [row0, row0+128) fp32 -> f16 swizzled smem (plain stores).
// ---------------------------------------------------------------------------
__device__ __forceinline__ void stage_z(const float* __restrict__ z, int row0,
                                        char* smem, int tid) {
    #pragma unroll
    for (int i = 0; i < 32; ++i) {
        int flat = i * 256 + tid;            // 8192 float4
        int r = flat >> 6, d4 = flat & 63;
        float4 v = *(const float4*)(z + (size_t)(row0 + r) * DD + d4 * 4);
        __half2 p0 = __float22half2_rn(make_float2(v.x, v.y));
        __half2 p1 = __float22half2_rn(make_float2(v.z, v.w));
        uint2 pk;
        pk.x = *(uint32_t*)&p0; pk.y = *(uint32_t*)&p1;
        uint32_t off = swz((uint32_t)((d4 >> 4) * 16384 + r * 128 + (d4 & 15) * 8));
        *(uint2*)(smem + ZH_OFF + off) = pk;
    }
}

// ---------------------------------------------------------------------------
// Pass 1 (balanced): 296 CTAs, static contiguous ranges over 2048 units
// (unit = row-block x 4-chunk group). Per-(thread, chunk-group) top-2 pools,
// flushed as packed u32 entries.  (round-10 proven MMA path, unchanged)
// ---------------------------------------------------------------------------
__global__ void __launch_bounds__(256, 2)
vq_pass1(const float* __restrict__ z) {
    extern __shared__ __align__(1024) char smem[];
    const uint32_t sb = smem_u32(smem);
    const int tid = threadIdx.x;
    const int lane = tid & 31;
    const int warp = tid >> 5;
    const int wm = warp >> 1;        // 0..3 (M)
    const int wn = warp & 1;         // 0..1 (N)
    const int g = lane >> 3;
    const int l7 = lane & 7;

    // static unit range: [cta*256/37, (cta+1)*256/37) ; 296*256 = 37*2048
    const int u0 = (blockIdx.x * 256) / 37;
    const int u1 = ((blockIdx.x + 1) * 256) / 37;
    const int A0 = u0 * 16, A1 = u1 * 16;    // absolute slice indices

    // prefetch w slices A0, A0+1
    load_wslice(A0, sb, tid); cp_commit();
    load_wslice(A0 + 1, sb, tid); cp_commit();

    int cur_rb = -1;
    int row0 = 0;

    float b0v[4], b1v[4];
    int   b0i[4], b1i[4];
    #pragma unroll
    for (int i = 0; i < 4; ++i) {
        b0v[i] = -FLT_MAX; b1v[i] = -FLT_MAX; b0i[i] = 0; b1i[i] = 0;
    }

    uint32_t acc[2][8][2];   // f16x2 accumulators

    for (int a = A0; a < A1; ++a) {
        const int rb = a >> 7, ch = (a >> 2) & 31, s = a & 3, buf = a & 1;

        if (rb != cur_rb) {              // new row-block: restage z
            __syncthreads();             // prior ldsm readers done
            cur_rb = rb;
            row0 = rb * 128;
            stage_z(z, row0, smem, tid);
        }

        cp_wait<1>();
        __syncthreads();

        if (s == 0) {
            #pragma unroll
            for (int mf = 0; mf < 2; ++mf)
                #pragma unroll
                for (int nf = 0; nf < 8; ++nf) {
                    acc[mf][nf][0] = 0u; acc[mf][nf][1] = 0u;
                }
        }

        const uint32_t wbase = sb + W_OFF + (uint32_t)(buf * 16384);
        #pragma unroll
        for (int ks = 0; ks < 4; ++ks) {
            uint32_t ah[2][4];
            #pragma unroll
            for (int mf = 0; mf < 2; ++mf) {
                uint32_t off = (uint32_t)((wm * 32 + mf * 16 + (g & 1) * 8 + l7) * 128
                                          + ks * 32 + ((g >> 1) << 4));
                ldsm4(ah[mf], sb + ZH_OFF + swz(off) + (uint32_t)(s * 16384));
            }
            uint32_t bh[4][4];
            #pragma unroll
            for (int p = 0; p < 4; ++p) {
                uint32_t off = (uint32_t)((wn * 64 + p * 16 + ((g >> 1) << 3) + l7) * 128
                                          + ks * 32 + ((g & 1) << 4));
                ldsm4(bh[p], wbase + swz(off));
            }
            #pragma unroll
            for (int mf = 0; mf < 2; ++mf)
                #pragma unroll
                for (int p = 0; p < 4; ++p) {
                    mma16816h(acc[mf][2 * p],     ah[mf], &bh[p][0]);
                    mma16816h(acc[mf][2 * p + 1], ah[mf], &bh[p][2]);
                }
        }

        __syncthreads();
        if (a + 2 < A1) load_wslice(a + 2, sb, tid);
        cp_commit();

        if (s == 3) {
            // update per-(thread,row-slot) top-2 over this chunk-group cell
            #pragma unroll
            for (int nf = 0; nf < 8; ++nf) {
                int col0 = ch * 128 + wn * 64 + nf * 8 + (lane & 3) * 2;
                #pragma unroll
                for (int mf = 0; mf < 2; ++mf) {
                    float2 p01 = __half22float2(*(__half2*)&acc[mf][nf][0]);
                    float2 p23 = __half22float2(*(__half2*)&acc[mf][nf][1]);
                    float vq[4] = {p01.x, p01.y, p23.x, p23.y};
                    #pragma unroll
                    for (int q = 0; q < 4; ++q) {
                        int sl = mf * 2 + (q >> 1);
                        float v = vq[q];
                        int c = col0 + (q & 1);
                        if (v > b1v[sl]) {
                            if (v > b0v[sl]) {
                                b1v[sl] = b0v[sl]; b1i[sl] = b0i[sl];
                                b0v[sl] = v;       b0i[sl] = c;
                            } else { b1v[sl] = v; b1i[sl] = c; }
                        }
                    }
                }
            }
            if ((a & 15) == 15) {
                // flush chunk-group pool: 2 packed entries per (thread,row-slot)
                int cg = (a >> 4) & 7;
                #pragma unroll
                for (int sl = 0; sl < 4; ++sl) {
                    int r = row0 + wm * 32 + (sl >> 1) * 16 + (sl & 1) * 8
                            + (lane >> 2);
                    int base = r * POOLW + cg * 16 + (wn * 4 + (lane & 3)) * 2;
                    uint2 pk;
                    pk.x = pack_cv(b0v[sl], b0i[sl]);
                    pk.y = pack_cv(b1v[sl], b1i[sl]);
                    *(uint2*)(g_pool + base) = pk;
                    b0v[sl] = -FLT_MAX; b1v[sl] = -FLT_MAX;
                    b0i[sl] = 0; b1i[sl] = 0;
                }
            }
        }
    }
}

// ---------------------------------------------------------------------------
// Pass 2 (fused output + final): per row, top-4 by approx from the packed
// 128-pool, exact fp32 rescore with reference rounding fl(fl(zsq+wsq)-2*dot)
// and first-index tie-break; z_q from winner registers; last block computes
// scalars.  (exact-rescore fma/shfl orders identical to rounds 3-11)
// ---------------------------------------------------------------------------
__global__ void __launch_bounds__(256)
vq_rescore(const float* __restrict__ z, const float* __restrict__ cb,
           float* __restrict__ out, int out_size) {
    const int lane = threadIdx.x & 31;
    const int row = blockIdx.x * 8 + (threadIdx.x >> 5);

    // z row: 8 dims per lane
    float zr[8];
    {
        float4 a = *(const float4*)(z + (size_t)row * DD + lane * 8);
        float4 b = *(const float4*)(z + (size_t)row * DD + lane * 8 + 4);
        zr[0] = a.x; zr[1] = a.y; zr[2] = a.z; zr[3] = a.w;
        zr[4] = b.x; zr[5] = b.y; zr[6] = b.z; zr[7] = b.w;
    }
    float zsq = 0.f;
    #pragma unroll
    for (int k = 0; k < 8; ++k) zsq += zr[k] * zr[k];
    #pragma unroll
    for (int o = 16; o > 0; o >>= 1) zsq += __shfl_xor_sync(0xffffffffu, zsq, o);

    // pool: 4 packed entries per lane
    float v[4]; int id[4];
    {
        uint4 pv = *(const uint4*)(g_pool + row * POOLW + lane * 4);
        uint32_t e[4] = {pv.x, pv.y, pv.z, pv.w};
        #pragma unroll
        for (int j = 0; j < 4; ++j) {
            v[j] = __half2float(__ushort_as_half((unsigned short)(e[j] >> 16)));
            id[j] = (int)(e[j] & 0xffffu);
        }
    }

    // select top-4 candidates by approx dot
    unsigned cons = 0u;
    int cand[4];
    #pragma unroll
    for (int t = 0; t < 4; ++t) {
        float m = -FLT_MAX; int mi = 0x7fffffff;
        #pragma unroll
        for (int j = 0; j < 4; ++j) {
            if (!((cons >> j) & 1u) &&
                (v[j] > m || (v[j] == m && id[j] < mi))) { m = v[j]; mi = id[j]; }
        }
        #pragma unroll
        for (int o = 16; o > 0; o >>= 1) {
            float mv = __shfl_xor_sync(0xffffffffu, m, o);
            int   mj = __shfl_xor_sync(0xffffffffu, mi, o);
            if (mv > m || (mv == m && mj < mi)) { m = mv; mi = mj; }
        }
        cand[t] = mi;
        #pragma unroll
        for (int j = 0; j < 4; ++j)
            if (id[j] == mi) cons |= 1u << j;
    }

    // prefetch all 4 candidate rows (MLP=8)
    float4 wa[4], wb[4];
    #pragma unroll
    for (int t = 0; t < 4; ++t) {
        const float* wp = cb + (size_t)cand[t] * DD + lane * 8;
        wa[t] = *(const float4*)wp;
        wb[t] = *(const float4*)(wp + 4);
    }

    // exact fp32 partial dots (same fma order as prior rounds)
    float dp[4];
    #pragma unroll
    for (int t = 0; t < 4; ++t) {
        float d = 0.f;
        d = fmaf(zr[0], wa[t].x, d); d = fmaf(zr[1], wa[t].y, d);
        d = fmaf(zr[2], wa[t].z, d); d = fmaf(zr[3], wa[t].w, d);
        d = fmaf(zr[4], wb[t].x, d); d = fmaf(zr[5], wb[t].y, d);
        d = fmaf(zr[6], wb[t].z, d); d = fmaf(zr[7], wb[t].w, d);
        dp[t] = d;
    }
    #pragma unroll
    for (int o = 16; o > 0; o >>= 1) {
        #pragma unroll
        for (int t = 0; t < 4; ++t)
            dp[t] += __shfl_xor_sync(0xffffffffu, dp[t], o);
    }

    float bdist = FLT_MAX;
    int   widx = 0x7fffffff;
    #pragma unroll
    for (int t = 0; t < 4; ++t) {
        float dist = (zsq + __ldg(&g_wsq[cand[t]])) - 2.f * dp[t];
        if (dist < bdist || (dist == bdist && cand[t] < widx)) {
            bdist = dist; widx = cand[t];
        }
    }

    // winner row already in registers: select it
    float4 oa = wa[0], ob = wb[0];
    #pragma unroll
    for (int t = 1; t < 4; ++t)
        if (cand[t] == widx) { oa = wa[t]; ob = wb[t]; }

    float lsum = 0.f;
    {
        float* op = out + (size_t)row * DD + lane * 8;
        if ((row + 1) * DD <= out_size) {
            *(float4*)op = oa;
            *(float4*)(op + 4) = ob;
        }
        float w8[8] = {oa.x, oa.y, oa.z, oa.w, ob.x, ob.y, ob.z, ob.w};
        #pragma unroll
        for (int k = 0; k < 8; ++k) {
            float dd = w8[k] - zr[k];
            lsum += dd * dd;
        }
    }
    #pragma unroll
    for (int o = 16; o > 0; o >>= 1) lsum += __shfl_xor_sync(0xffffffffu, lsum, o);

    if (lane == 0) {
        atomicAdd(&g_counts[widx], 1u);
        atomicAdd(&g_loss, (double)lsum);
        int pos = BB * DD + row;
        if (pos < out_size) out[pos] = (float)widx;
        __threadfence();
    }

    // ---- fused finalization: last block computes scalars ----
    __shared__ int slast;
    __shared__ double red[8];
    __syncthreads();
    if (threadIdx.x == 0)
        slast = (atomicAdd(&g_done, 1u) == (unsigned)(gridDim.x - 1)) ? 1 : 0;
    __syncthreads();
    if (slast) {
        int t = threadIdx.x;
        double s = 0.0;
        for (int k = t; k < KK; k += 256) {
            unsigned c = atomicAdd(&g_counts[k], 0u);   // coherent read
            float p = (float)c / (float)BB;
            s += (double)(p * logf(p + 1e-10f));
        }
        #pragma unroll
        for (int o = 16; o > 0; o >>= 1) s += __shfl_xor_sync(0xffffffffu, s, o);
        if ((t & 31) == 0) red[t >> 5] = s;
        __syncthreads();
        if (t < 32) {
            double vv = (t < 8) ? red[t] : 0.0;
            #pragma unroll
            for (int o = 4; o > 0; o >>= 1) vv += __shfl_xor_sync(0xffffffffu, vv, o);
            if (t == 0) {
                double loss = atomicAdd(&g_loss, 0.0);  // coherent read
                int p0 = BB * DD + BB;
                if (p0 < out_size)
                    out[p0] = (float)(loss / ((double)BB * (double)DD) * 1.25);
                if (p0 + 1 < out_size)
                    out[p0 + 1] = expf((float)(-vv));
            }
        }
    }
}

// ---------------------------------------------------------------------------
extern "C" void kernel_launch(void* const* d_in, const int* in_sizes, int n_in,
                              void* d_out, int out_size) {
    const float* z  = (const float*)d_in[0];   // z_e [32768, 256] f32
    const float* cb = (const float*)d_in[1];   // codebook [4096, 256] f32
    float* out = (float*)d_out;

    cudaFuncSetAttribute(vq_pass1,
                         cudaFuncAttributeMaxDynamicSharedMemorySize, SMEM_BYTES);

    conv_w<<<KK / 8, 256>>>(cb);
    vq_pass1<<<GRID1, 256, SMEM_BYTES>>>(z);
    vq_rescore<<<BB / 8, 256>>>(z, cb, out, out_size);
}